// round 17
// baseline (speedup 1.0000x reference)
#include <cuda_runtime.h>
#include <cuda_fp16.h>
#include <cstdint>

#define N_PTS   32768
#define DIM     256
#define KCODES  1024
#define NTILES  8                // KCODES / 128
#define TC      32               // per-(point,tile) candidate capacity
#define DECAYF  0.99f
#define OMDECAY 0.01f
#define EPSF    1e-5f
#define MARGIN  2.0f
#define CMAX    32

// Output layout (concatenated, float32)
#define OFF_ZQ    0
#define OFF_LOSS  (N_PTS * DIM)
#define OFF_IDX   (OFF_LOSS + 1)
#define OFF_EMB   (OFF_IDX + N_PTS)
#define OFF_CS    (OFF_EMB + KCODES * DIM)
#define OFF_EMAW  (OFF_CS + KCODES)

__device__ float    g_enorm[KCODES];
__device__ float    g_loss;
__device__ float    g_n;
__device__ __half   g_zh[N_PTS * DIM];
__device__ __half   g_eh[KCODES * DIM];
__device__ float    g_tmin[N_PTS * NTILES];
__device__ int      g_tcnt[N_PTS * NTILES];
__device__ uint32_t g_tcand[N_PTS * NTILES * TC];   // (halfbits<<16)|code
__device__ int      g_sel[N_PTS];
__device__ int      g_cnt[KCODES];
__device__ int      g_off[KCODES];
__device__ int      g_fill[KCODES];
__device__ int      g_bkt[N_PTS];

// ---------------------------------------------------------------------------
// helpers
// ---------------------------------------------------------------------------
__device__ __forceinline__ uint32_t smem_u32(const void* p) {
    uint32_t a;
    asm("{ .reg .u64 t; cvta.to.shared.u64 t, %1; cvt.u32.u64 %0, t; }"
        : "=r"(a) : "l"(p));
    return a;
}
__device__ __forceinline__ void cp16(uint32_t dst, const void* src) {
    asm volatile("cp.async.cg.shared.global [%0], [%1], 16;"
                 :: "r"(dst), "l"(__cvta_generic_to_global(src)) : "memory");
}
#define CP_COMMIT() asm volatile("cp.async.commit_group;" ::: "memory")

#define LDSM_X4(r0, r1, r2, r3, a) \
    asm volatile("ldmatrix.sync.aligned.m8n8.x4.shared.b16 {%0,%1,%2,%3}, [%4];" \
                 : "=r"(r0), "=r"(r1), "=r"(r2), "=r"(r3) : "r"(a))
#define LDSM_X2(r0, r1, a) \
    asm volatile("ldmatrix.sync.aligned.m8n8.x2.shared.b16 {%0,%1}, [%2];" \
                 : "=r"(r0), "=r"(r1) : "r"(a))

__device__ __forceinline__ void mma16816(float* c, const uint32_t* a, const uint32_t* b) {
    asm volatile("mma.sync.aligned.m16n8k16.row.col.f32.f16.f16.f32 "
                 "{%0,%1,%2,%3}, {%4,%5,%6,%7}, {%8,%9}, {%0,%1,%2,%3};"
                 : "+f"(c[0]), "+f"(c[1]), "+f"(c[2]), "+f"(c[3])
                 : "r"(a[0]), "r"(a[1]), "r"(a[2]), "r"(a[3]), "r"(b[0]), "r"(b[1]));
}

__device__ __forceinline__ uint32_t ordf(float f) {
    uint32_t b = __float_as_uint(f);
    return (b & 0x80000000u) ? ~b : (b | 0x80000000u);
}
__device__ __forceinline__ float unordf(uint32_t u) {
    uint32_t b = (u & 0x80000000u) ? (u & 0x7FFFFFFFu) : ~u;
    return __uint_as_float(b);
}
__device__ __forceinline__ uint32_t packcand(float d, int code) {
    return ((uint32_t)__half_as_ushort(__float2half_rn(d)) << 16) | (uint32_t)code;
}

// ---------------------------------------------------------------------------
// k_prep: fp32 -> fp16 (vectorized); zero counters
// ---------------------------------------------------------------------------
__global__ void k_prep(const float* __restrict__ z, const float* __restrict__ e) {
    int idx = blockIdx.x * blockDim.x + threadIdx.x;     // covers N*D/4 = 2M
    int i4 = idx * 4;
    float4 v = *(const float4*)(z + i4);
    __half2* zp = (__half2*)(g_zh + i4);
    zp[0] = __floats2half2_rn(v.x, v.y);
    zp[1] = __floats2half2_rn(v.z, v.w);
    if (i4 < KCODES * DIM) {
        float4 w = *(const float4*)(e + i4);
        __half2* ep = (__half2*)(g_eh + i4);
        ep[0] = __floats2half2_rn(w.x, w.y);
        ep[1] = __floats2half2_rn(w.z, w.w);
    }
    if (idx < N_PTS * NTILES) g_tcnt[idx] = 0;
    if (idx < KCODES) { g_cnt[idx] = 0; g_fill[idx] = 0; }
    if (idx == 0) g_loss = 0.0f;
}

__global__ void k_norm(const float* __restrict__ emb) {
    int warp = (blockIdx.x * blockDim.x + threadIdx.x) >> 5;
    int lane = threadIdx.x & 31;
    if (warp >= KCODES) return;
    const float4* row = (const float4*)(emb + (size_t)warp * DIM);
    float4 a = row[lane * 2 + 0];
    float4 b = row[lane * 2 + 1];
    float s = a.x*a.x + a.y*a.y + a.z*a.z + a.w*a.w
            + b.x*b.x + b.y*b.y + b.z*b.z + b.w*b.w;
#pragma unroll
    for (int off = 16; off; off >>= 1) s += __shfl_down_sync(0xFFFFFFFFu, s, off);
    if (lane == 0) g_enorm[warp] = s;
}

// ---------------------------------------------------------------------------
// HMMA fp16 distance GEMM (R9-proven mainloop) + candidate-emitting epilogue.
// No distance matrix is materialized.
// ---------------------------------------------------------------------------
#define ROWB    144                      // 64 halves data + 8 pad
#define EN_OFF  0
#define MK_OFF  512                      // 128 x uint32 row-min
#define ST_A(s) (1024 + (s) * 36864)
#define ST_B(s) (1024 + (s) * 36864 + 18432)
#define SMEM_SZ (1024 + 2 * 36864)       // 74752

__device__ __forceinline__ void load_stage(uint32_t sb, int s, int m0, int n0,
                                           int kk, int tid) {
#pragma unroll
    for (int i = 0; i < 4; i++) {
        int ch = tid + i * 256;
        int r = ch >> 3, sg = ch & 7;
        uint32_t o = (uint32_t)(r * ROWB + sg * 16);
        cp16(sb + ST_A(s) + o, g_zh + (size_t)(m0 + r) * DIM + kk + sg * 8);
        cp16(sb + ST_B(s) + o, g_eh + (size_t)(n0 + r) * DIM + kk + sg * 8);
    }
}

__global__ __launch_bounds__(256, 2) void k_dist_hmma() {
    extern __shared__ char smem[];
    uint32_t sb = smem_u32(smem);
    int tid = threadIdx.x;
    int wid = tid >> 5;
    int lane = tid & 31;
    int tileN = blockIdx.x;              // code tile 0..7
    int n0 = tileN * 128;
    int m0 = blockIdx.y * 128;
    int warp_m = wid & 1;
    int warp_n = wid >> 1;

    float*    en   = (float*)(smem + EN_OFF);
    uint32_t* mink = (uint32_t*)(smem + MK_OFF);

    if (tid < 128) { en[tid] = g_enorm[n0 + tid]; mink[tid] = 0xFFFFFFFFu; }

    float acc[4][4][4] = {};

    int rA = warp_m * 64 + (lane & 7) + (((lane >> 3) & 1) << 3);
    int cA8 = ((lane >> 4) & 1) << 3;
    int rB = warp_n * 32 + (lane & 7);
    int cB8 = ((lane >> 3) & 1) << 3;

    load_stage(sb, 0, m0, n0, 0, tid); CP_COMMIT();
    load_stage(sb, 1, m0, n0, 64, tid); CP_COMMIT();

    for (int c = 0; c < 4; c++) {
        int s = c & 1;
        if (c < 3) asm volatile("cp.async.wait_group 1;" ::: "memory");
        else       asm volatile("cp.async.wait_group 0;" ::: "memory");
        __syncthreads();

#pragma unroll
        for (int ks = 0; ks < 4; ks++) {
            int k0 = ks * 16;
            uint32_t a[4][4], b[4][2];
#pragma unroll
            for (int mi = 0; mi < 4; mi++) {
                uint32_t ad = sb + ST_A(s) + (rA + mi * 16) * ROWB + (k0 + cA8) * 2;
                LDSM_X4(a[mi][0], a[mi][1], a[mi][2], a[mi][3], ad);
            }
#pragma unroll
            for (int nj = 0; nj < 4; nj++) {
                uint32_t bd = sb + ST_B(s) + (rB + nj * 8) * ROWB + (k0 + cB8) * 2;
                LDSM_X2(b[nj][0], b[nj][1], bd);
            }
#pragma unroll
            for (int mi = 0; mi < 4; mi++)
#pragma unroll
                for (int nj = 0; nj < 4; nj++)
                    mma16816(acc[mi][nj], a[mi], b[nj]);
        }
        __syncthreads();
        if (c + 2 < 4) { load_stage(sb, s, m0, n0, (c + 2) * 64, tid); CP_COMMIT(); }
    }

    // ---- pass 1: per-row tile min (R13-proven reduction) ----
#pragma unroll
    for (int mi = 0; mi < 4; mi++) {
        float v0 = 3.4e38f, v1 = 3.4e38f;
#pragma unroll
        for (int nj = 0; nj < 4; nj++) {
            int cw = warp_n * 32 + nj * 8 + (lane & 3) * 2;
            float e0 = en[cw], e1 = en[cw + 1];
            v0 = fminf(v0, fminf(e0 - 2.0f * acc[mi][nj][0],
                                 e1 - 2.0f * acc[mi][nj][1]));
            v1 = fminf(v1, fminf(e0 - 2.0f * acc[mi][nj][2],
                                 e1 - 2.0f * acc[mi][nj][3]));
        }
#pragma unroll
        for (int off = 1; off < 4; off <<= 1) {
            v0 = fminf(v0, __shfl_xor_sync(0xFFFFFFFFu, v0, off));
            v1 = fminf(v1, __shfl_xor_sync(0xFFFFFFFFu, v1, off));
        }
        if ((lane & 3) == 0) {
            int r0 = warp_m * 64 + mi * 16 + (lane >> 2);
            atomicMin(&mink[r0],     ordf(v0));
            atomicMin(&mink[r0 + 8], ordf(v1));
        }
    }
    __syncthreads();

    if (tid < 128)
        g_tmin[(size_t)(m0 + tid) * NTILES + tileN] = unordf(mink[tid]);

    // ---- pass 2: emit candidates within tile_min + MARGIN ----
#pragma unroll
    for (int mi = 0; mi < 4; mi++) {
        int r0 = warp_m * 64 + mi * 16 + (lane >> 2);
        int r1 = r0 + 8;
        float t0 = unordf(mink[r0]) + MARGIN;
        float t1 = unordf(mink[r1]) + MARGIN;
        int base0 = (m0 + r0) * NTILES + tileN;
        int base1 = (m0 + r1) * NTILES + tileN;
#pragma unroll
        for (int nj = 0; nj < 4; nj++) {
            int cw = warp_n * 32 + nj * 8 + (lane & 3) * 2;
            float e0 = en[cw], e1 = en[cw + 1];
            float d00 = e0 - 2.0f * acc[mi][nj][0];
            float d01 = e1 - 2.0f * acc[mi][nj][1];
            float d10 = e0 - 2.0f * acc[mi][nj][2];
            float d11 = e1 - 2.0f * acc[mi][nj][3];
            if (d00 <= t0) { int p = atomicAdd(&g_tcnt[base0], 1);
                if (p < TC) g_tcand[(size_t)base0 * TC + p] = packcand(d00, n0 + cw); }
            if (d01 <= t0) { int p = atomicAdd(&g_tcnt[base0], 1);
                if (p < TC) g_tcand[(size_t)base0 * TC + p] = packcand(d01, n0 + cw + 1); }
            if (d10 <= t1) { int p = atomicAdd(&g_tcnt[base1], 1);
                if (p < TC) g_tcand[(size_t)base1 * TC + p] = packcand(d10, n0 + cw); }
            if (d11 <= t1) { int p = atomicAdd(&g_tcnt[base1], 1);
                if (p < TC) g_tcand[(size_t)base1 * TC + p] = packcand(d11, n0 + cw + 1); }
        }
    }
}

// ---------------------------------------------------------------------------
// k_selgather: warp per point. Global min from 8 tile-mins -> filter recorded
// candidates -> exact fp32 rescore -> fused gather (z_q, idx, loss, counts).
// ---------------------------------------------------------------------------
__global__ __launch_bounds__(256) void k_selgather(const float* __restrict__ z,
                                                   const float* __restrict__ emb,
                                                   float* __restrict__ out) {
    __shared__ int s_cnt[8];
    __shared__ int s_list[8][CMAX];
    __shared__ float warp_loss[8];
    int w = threadIdx.x >> 5;
    int lane = threadIdx.x & 31;
    int n = blockIdx.x * 8 + w;

    if (lane == 0) s_cnt[w] = 0;
    __syncwarp();

    // global approx min over 8 tiles (lanes 0-7 hold tile mins)
    float tm = (lane < NTILES) ? g_tmin[(size_t)n * NTILES + lane] : 3.4e38f;
#pragma unroll
    for (int off = 4; off; off >>= 1)
        tm = fminf(tm, __shfl_xor_sync(0xFFFFFFFFu, tm, off));
    float thr = __shfl_sync(0xFFFFFFFFu, tm, 0) + MARGIN;

    // filter recorded candidates (lanes 0-7, one tile each)
    if (lane < NTILES) {
        int base = n * NTILES + lane;
        int cnt = min(g_tcnt[base], TC);
        const uint32_t* lst = g_tcand + (size_t)base * TC;
        for (int i = 0; i < cnt; i++) {
            uint32_t e = lst[i];
            float d = __half2float(__ushort_as_half((unsigned short)(e >> 16)));
            if (d <= thr) {
                int p = atomicAdd(&s_cnt[w], 1);
                if (p < CMAX) s_list[w][p] = (int)(e & 0xFFFFu);
            }
        }
    }
    __syncwarp();
    int cnt = min(s_cnt[w], CMAX);

    const float4* zr = (const float4*)(z + (size_t)n * DIM);
    float4 za = zr[lane * 2], zb = zr[lane * 2 + 1];

    float bd = 3.4e38f;
    int bc = 0x7FFFFFFF;
    for (int t = 0; t < cnt; t++) {
        int c = s_list[w][t];
        const float4* er = (const float4*)(emb + (size_t)c * DIM);
        float4 ea = er[lane * 2], eb = er[lane * 2 + 1];
        float s = za.x*ea.x + za.y*ea.y + za.z*ea.z + za.w*ea.w
                + zb.x*eb.x + zb.y*eb.y + zb.z*eb.z + zb.w*eb.w;
#pragma unroll
        for (int off = 16; off; off >>= 1)
            s += __shfl_xor_sync(0xFFFFFFFFu, s, off);
        float d = g_enorm[c] - 2.0f * s;
        if (d < bd || (d == bd && c < bc)) { bd = d; bc = c; }
    }

    // fused gather + loss
    const float4* er = (const float4*)(emb + (size_t)bc * DIM);
    float4 ea = er[lane * 2], eb = er[lane * 2 + 1];
    float4* zq = (float4*)(out + OFF_ZQ + (size_t)n * DIM);
    zq[lane * 2]     = ea;
    zq[lane * 2 + 1] = eb;
    float lsum;
    {
        float dx = za.x-ea.x, dy = za.y-ea.y, dz = za.z-ea.z, dw = za.w-ea.w;
        lsum = dx*dx + dy*dy + dz*dz + dw*dw;
        dx = zb.x-eb.x; dy = zb.y-eb.y; dz = zb.z-eb.z; dw = zb.w-eb.w;
        lsum += dx*dx + dy*dy + dz*dz + dw*dw;
    }
#pragma unroll
    for (int off = 16; off; off >>= 1)
        lsum += __shfl_down_sync(0xFFFFFFFFu, lsum, off);
    if (lane == 0) {
        out[OFF_IDX + n] = (float)bc;
        g_sel[n] = bc;
        atomicAdd(&g_cnt[bc], 1);
        warp_loss[w] = lsum;
    }
    __syncthreads();
    if (threadIdx.x == 0) {
        float s = 0.0f;
#pragma unroll
        for (int i = 0; i < 8; i++) s += warp_loss[i];
        atomicAdd(&g_loss, s);
    }
}

// ---------------------------------------------------------------------------
// k_off: warp-shuffle exclusive scan of counts; new_cluster_size; fused n-sum
// ---------------------------------------------------------------------------
__global__ void k_off(const float* __restrict__ ema_cs, float* __restrict__ out) {
    __shared__ int   sh[32];
    __shared__ float fs[32];
    int t = threadIdx.x;
    int lane = t & 31, w = t >> 5;
    int v = g_cnt[t];
    float cs = DECAYF * ema_cs[t] + OMDECAY * (float)v;
    out[OFF_CS + t] = cs;

    int incl = v;
#pragma unroll
    for (int off = 1; off < 32; off <<= 1) {
        int x = __shfl_up_sync(0xFFFFFFFFu, incl, off);
        if (lane >= off) incl += x;
    }
    if (lane == 31) sh[w] = incl;

    float r = cs;
#pragma unroll
    for (int off = 16; off; off >>= 1) r += __shfl_down_sync(0xFFFFFFFFu, r, off);
    if (lane == 0) fs[w] = r;

    __syncthreads();
    if (w == 0) {
        int s = sh[lane];
        int inc = s;
#pragma unroll
        for (int off = 1; off < 32; off <<= 1) {
            int x = __shfl_up_sync(0xFFFFFFFFu, inc, off);
            if (lane >= off) inc += x;
        }
        sh[lane] = inc - s;

        float fsum = fs[lane];
#pragma unroll
        for (int off = 16; off; off >>= 1)
            fsum += __shfl_down_sync(0xFFFFFFFFu, fsum, off);
        if (lane == 0) g_n = fsum;
    }
    __syncthreads();
    g_off[t] = sh[w] + incl - v;
}

__global__ void k_fill() {
    int n = blockIdx.x * blockDim.x + threadIdx.x;
    int c = g_sel[n];
    int pos = g_off[c] + atomicAdd(&g_fill[c], 1);
    g_bkt[pos] = n;
}

__global__ __launch_bounds__(256) void k_dw(const float* __restrict__ z,
                                            const float* __restrict__ ema_w,
                                            float* __restrict__ out) {
    int c = blockIdx.x;
    int d = threadIdx.x;
    int beg = g_off[c], cnt = g_cnt[c];
    float acc = 0.0f;
    for (int m = 0; m < cnt; m++) {
        int p = g_bkt[beg + m];
        acc += z[(size_t)p * DIM + d];
    }
    out[OFF_EMAW + (size_t)c * DIM + d] =
        DECAYF * ema_w[(size_t)c * DIM + d] + OMDECAY * acc;
}

__global__ void k_final(float* __restrict__ out) {
    int i = blockIdx.x * blockDim.x + threadIdx.x;
    float n = g_n;
    int k = i >> 8;
    float cs = (out[OFF_CS + k] + EPSF) / (n + (float)KCODES * EPSF) * n;
    out[OFF_EMB + i] = out[OFF_EMAW + i] / cs;
    if (i == 0)
        out[OFF_LOSS] = 1.25f * g_loss / (float)(N_PTS * DIM);
}

// ---------------------------------------------------------------------------
extern "C" void kernel_launch(void* const* d_in, const int* in_sizes, int n_in,
                              void* d_out, int out_size) {
    const float* z      = (const float*)d_in[0];
    const float* emb    = (const float*)d_in[1];
    const float* ema_cs = (const float*)d_in[2];
    const float* ema_w  = (const float*)d_in[3];
    float* out = (float*)d_out;

    cudaFuncSetAttribute(k_dist_hmma,
                         cudaFuncAttributeMaxDynamicSharedMemorySize, SMEM_SZ);

    k_prep<<<(N_PTS * DIM / 4) / 256, 256>>>(z, emb);
    k_norm<<<(KCODES * 32) / 256, 256>>>(emb);
    k_dist_hmma<<<dim3(NTILES, N_PTS / 128), 256, SMEM_SZ>>>();
    k_selgather<<<N_PTS / 8, 256>>>(z, emb, out);
    k_off<<<1, KCODES>>>(ema_cs, out);
    k_fill<<<N_PTS / 256, 256>>>();
    k_dw<<<KCODES, 256>>>(z, ema_w, out);
    k_final<<<(KCODES * DIM) / 256, 256>>>(out);
}